// round 7
// baseline (speedup 1.0000x reference)
#include <cuda_runtime.h>
#include <cstdint>

// out[o,i,h,w] = sum_k weights[o,i,k] * x[k,h,w]
// OUT_CH = IN_CH = 2048, x is 3x3x3, output is (2048,2048,3,3) fp32.
//
// Each thread computes 2 (o,i) pairs (18 floats) and stages them in shared
// memory. Drain is WARP-granular: each warp's 64 pairs are a contiguous
// 2304B slice, stored with its own 1D TMA bulk store issued as soon as the
// warp's staging is done (no block-wide barrier), so compute and drain
// overlap within and across blocks.

__global__ void __launch_bounds__(256, 6) gf_layer_kernel(
    const float* __restrict__ x,
    const float* __restrict__ w,
    float* __restrict__ out) {
    __shared__ alignas(128) float sout[256 * 18];  // 18 KB staging tile
    __shared__ alignas(16) float xs[28];

    const int tid = threadIdx.x;
    if (tid < 27) xs[tid] = x[tid];
    __syncthreads();

    // First (o,i) pair handled by this thread (2 pairs per thread).
    const long long p = ((long long)blockIdx.x * 256 + tid) * 2;

    // 6 contiguous weights (2 pairs x 3 coeffs); byte offset p*12 is
    // 24B-aligned -> 3x float2 loads. w (50MB) stays L2-resident.
    const float2* __restrict__ w2 = reinterpret_cast<const float2*>(w + p * 3);
    const float2 wa = w2[0];
    const float2 wb = w2[1];
    const float2 wc = w2[2];
    const float wv[6] = {wa.x, wa.y, wb.x, wb.y, wc.x, wc.y};

    float o[18];
#pragma unroll
    for (int pp = 0; pp < 2; pp++) {
        const float c0 = wv[pp * 3 + 0];
        const float c1 = wv[pp * 3 + 1];
        const float c2 = wv[pp * 3 + 2];
#pragma unroll
        for (int j = 0; j < 9; j++) {
            o[pp * 9 + j] = fmaf(c0, xs[j], fmaf(c1, xs[9 + j], c2 * xs[18 + j]));
        }
    }

    // Stage to smem as float2: thread stride = 18 floats = 72B. STS.64 phase
    // = 16 lanes; banks (18*l) mod 32 are 16 distinct even values ->
    // conflict-free.
    float2* __restrict__ s2 = reinterpret_cast<float2*>(sout + tid * 18);
#pragma unroll
    for (int i = 0; i < 9; i++) {
        s2[i] = make_float2(o[2 * i], o[2 * i + 1]);
    }

    // Per-warp TMA drain: warp wid owns sout[wid*576 .. +576) = 2304 bytes,
    // contiguous in both smem and gmem.
    const int wid = tid >> 5;
    const int lid = tid & 31;
    __syncwarp();

    if (lid == 0) {
        const float* ssrc = sout + wid * (32 * 18);
        uint32_t saddr;
        asm("{ .reg .u64 t; cvta.to.shared.u64 t, %1; cvt.u32.u64 %0, t; }"
            : "=r"(saddr) : "l"(ssrc));
        float* gdst = out + (long long)blockIdx.x * (256 * 18) + wid * (32 * 18);
        asm volatile("fence.proxy.async.shared::cta;" ::: "memory");
        asm volatile(
            "cp.async.bulk.global.shared::cta.bulk_group [%0], [%1], %2;"
            :: "l"(gdst), "r"(saddr), "r"(32 * 18 * 4) : "memory");
        asm volatile("cp.async.bulk.commit_group;" ::: "memory");
        // Wait before this warp's smem slice may be torn down (block exit).
        asm volatile("cp.async.bulk.wait_group 0;" ::: "memory");
    }
}

extern "C" void kernel_launch(void* const* d_in, const int* in_sizes, int n_in,
                              void* d_out, int out_size) {
    // Inputs: x (27 elems), weights (2048*2048*3). Identify x by element count.
    const float* x;
    const float* w;
    long long w_elems;
    if (in_sizes[0] == 27) {
        x = (const float*)d_in[0];
        w = (const float*)d_in[1];
        w_elems = in_sizes[1];
    } else {
        x = (const float*)d_in[1];
        w = (const float*)d_in[0];
        w_elems = in_sizes[0];
    }

    float* out = (float*)d_out;

    const long long total_pairs = w_elems / 3;   // (o,i) pairs = 4,194,304
    const long long pairs_per_block = 256 * 2;   // 512
    const int blocks = (int)(total_pairs / pairs_per_block);  // 8192, exact

    gf_layer_kernel<<<blocks, 256>>>(x, w, out);
}

// round 8
// speedup vs baseline: 1.0073x; 1.0073x over previous
#include <cuda_runtime.h>
#include <cstdint>

// out[o,i,h,w] = sum_k weights[o,i,k] * x[k,h,w]
// OUT_CH = IN_CH = 2048, x is 3x3x3, output is (2048,2048,3,3) fp32.
//
// Double-buffered streaming kernel. Each block covers 1024 (o,i) pairs in two
// 512-pair tiles. Per tile: each thread computes 2 pairs (18 floats), stages
// into that tile's smem buffer, and each warp drains its contiguous 2304B
// slice with its own 1D TMA bulk store. Tile1's compute overlaps tile0's TMA
// flight; a single wait_group 0 at the end covers both commits.

__global__ void __launch_bounds__(256, 5) gf_layer_kernel(
    const float* __restrict__ x,
    const float* __restrict__ w,
    float* __restrict__ out) {
    __shared__ alignas(128) float sout[2][256 * 18];  // 2 x 18 KB buffers
    __shared__ alignas(16) float xs[28];

    const int tid = threadIdx.x;
    if (tid < 27) xs[tid] = x[tid];
    __syncthreads();

    const int wid = tid >> 5;
    const int lid = tid & 31;
    const long long block_pair0 = (long long)blockIdx.x * 1024;

#pragma unroll
    for (int t = 0; t < 2; t++) {
        // First (o,i) pair for this thread in tile t.
        const long long p = block_pair0 + t * 512 + tid * 2;

        // 6 contiguous weights (2 pairs x 3 coeffs); byte offset p*12 is
        // 24B-aligned -> 3x float2 loads. w (50MB) stays L2-resident.
        const float2* __restrict__ w2 =
            reinterpret_cast<const float2*>(w + p * 3);
        const float2 wa = w2[0];
        const float2 wb = w2[1];
        const float2 wc = w2[2];
        const float wv[6] = {wa.x, wa.y, wb.x, wb.y, wc.x, wc.y};

        float o[18];
#pragma unroll
        for (int pp = 0; pp < 2; pp++) {
            const float c0 = wv[pp * 3 + 0];
            const float c1 = wv[pp * 3 + 1];
            const float c2 = wv[pp * 3 + 2];
#pragma unroll
            for (int j = 0; j < 9; j++) {
                o[pp * 9 + j] =
                    fmaf(c0, xs[j], fmaf(c1, xs[9 + j], c2 * xs[18 + j]));
            }
        }

        // Stage to smem as float2: thread stride = 18 floats = 72B. STS.64
        // phase = 16 lanes; banks (18*l) mod 32 are 16 distinct even values
        // -> conflict-free.
        float2* __restrict__ s2 =
            reinterpret_cast<float2*>(&sout[t][0] + tid * 18);
#pragma unroll
        for (int i = 0; i < 9; i++) {
            s2[i] = make_float2(o[2 * i], o[2 * i + 1]);
        }

        __syncwarp();

        // Per-warp TMA drain: warp wid owns 2304 contiguous bytes of tile t.
        if (lid == 0) {
            const float* ssrc = &sout[t][0] + wid * (32 * 18);
            uint32_t saddr;
            asm("{ .reg .u64 q; cvta.to.shared.u64 q, %1; cvt.u32.u64 %0, q; }"
                : "=r"(saddr) : "l"(ssrc));
            float* gdst =
                out + (block_pair0 + t * 512) * 9 + wid * (32 * 18);
            asm volatile("fence.proxy.async.shared::cta;" ::: "memory");
            asm volatile(
                "cp.async.bulk.global.shared::cta.bulk_group [%0], [%1], %2;"
                :: "l"(gdst), "r"(saddr), "r"(32 * 18 * 4) : "memory");
            asm volatile("cp.async.bulk.commit_group;" ::: "memory");
        }
    }

    // Single wait for both in-flight bulk stores before smem teardown.
    if (lid == 0) {
        asm volatile("cp.async.bulk.wait_group 0;" ::: "memory");
    }
}

extern "C" void kernel_launch(void* const* d_in, const int* in_sizes, int n_in,
                              void* d_out, int out_size) {
    // Inputs: x (27 elems), weights (2048*2048*3). Identify x by element count.
    const float* x;
    const float* w;
    long long w_elems;
    if (in_sizes[0] == 27) {
        x = (const float*)d_in[0];
        w = (const float*)d_in[1];
        w_elems = in_sizes[1];
    } else {
        x = (const float*)d_in[1];
        w = (const float*)d_in[0];
        w_elems = in_sizes[0];
    }

    float* out = (float*)d_out;

    const long long total_pairs = w_elems / 3;    // (o,i) pairs = 4,194,304
    const long long pairs_per_block = 1024;      // 2 tiles x 512
    const int blocks = (int)(total_pairs / pairs_per_block);  // 4096, exact

    gf_layer_kernel<<<blocks, 256>>>(x, w, out);
}